// round 5
// baseline (speedup 1.0000x reference)
#include <cuda_runtime.h>
#include <cuda_bf16.h>
#include <math.h>

// Problem constants
#define H     96
#define W     96
#define HW    9216           // H*W
#define C     64
#define T     7
#define NB    12             // 6 backward + 6 forward frame pairs
#define CIN1  130            // warped(64) + x_cur(64) + flow(2)
#define COUT4 432            // 3 * 9 * 16
#define NEG   0.1f

// ---------------------------------------------------------------------------
// Packed fp32x2 helpers (sm_100a FFMA2 path — 2 fp32 FMAs per issue slot)
// ---------------------------------------------------------------------------
__device__ __forceinline__ void ffma2(unsigned long long& d,
                                      unsigned long long a,
                                      unsigned long long b) {
    asm("fma.rn.f32x2 %0, %1, %2, %0;" : "+l"(d) : "l"(a), "l"(b));
}
__device__ __forceinline__ unsigned long long pack2(float lo, float hi) {
    unsigned long long r;
    asm("mov.b64 %0, {%1, %2};" : "=l"(r) : "f"(lo), "f"(hi));
    return r;
}
__device__ __forceinline__ float2 unpack2(unsigned long long v) {
    float2 r;
    asm("mov.b64 {%0, %1}, %2;" : "=f"(r.x), "=f"(r.y) : "l"(v));
    return r;
}

// Fast tanh / sigmoid on MUFU EX2/RCP (rel err ~1e-6 — negligible here).
__device__ __forceinline__ float fast_tanh(float x) {
    float xc = fminf(fmaxf(x, -15.f), 15.f);
    float e = __expf(2.f * xc);
    return __fdividef(e - 1.f, e + 1.f);
}
__device__ __forceinline__ float fast_sigmoid(float x) {
    float xc = fminf(fmaxf(x, -30.f), 30.f);
    return __fdividef(1.f, 1.f + __expf(-xc));
}

// ---------------------------------------------------------------------------
// Scratch buffers (device globals -- no allocation allowed in kernel_launch)
// ---------------------------------------------------------------------------
__device__ float g_h0[NB * CIN1 * HW];    // concat input
__device__ float g_h1[NB * C * HW];       // conv1 out / conv3 out
__device__ float g_h2[NB * C * HW];       // conv2 out
__device__ float g_o4[NB * COUT4 * HW];   // conv4 out
__device__ float g_samp[NB * 576 * HW];   // deform samples (255 MB)
__device__ float g_xt[T * HW * C];        // x transposed to NHWC (16.5 MB)

// ---------------------------------------------------------------------------
// Zero only the two frames deform never writes (bwd[6], fwd[0])
// ---------------------------------------------------------------------------
__global__ void zero_k(float4* __restrict__ p, int n4) {
    int i = blockIdx.x * blockDim.x + threadIdx.x;
    if (i < n4) p[i] = make_float4(0.f, 0.f, 0.f, 0.f);
}

// ---------------------------------------------------------------------------
// NCHW -> NHWC transpose of x: g_xt[t][pix][64].
// One thread per (t,pix): 64 coalesced scalar reads, 16 float4 writes.
// ---------------------------------------------------------------------------
__global__ void nhwc_k(const float* __restrict__ x, float4* __restrict__ xt4) {
    int p = blockIdx.x * blockDim.x + threadIdx.x;
    if (p >= T * HW) return;
    int t = p / HW, pix = p % HW;
    const float* xn = x + (size_t)t * C * HW + pix;
    float4* dst = xt4 + (size_t)p * (C / 4);
    #pragma unroll
    for (int cb = 0; cb < C / 4; cb++) {
        float4 v;
        v.x = xn[(size_t)(4 * cb + 0) * HW];
        v.y = xn[(size_t)(4 * cb + 1) * HW];
        v.z = xn[(size_t)(4 * cb + 2) * HW];
        v.w = xn[(size_t)(4 * cb + 3) * HW];
        dst[cb] = v;
    }
}

// ---------------------------------------------------------------------------
// Stage 1: flow-warp x_src (NHWC float4 gathers) + concat build.
// ---------------------------------------------------------------------------
__global__ void warp_concat_k(const float* __restrict__ x,
                              const float4* __restrict__ xt4,
                              const float* __restrict__ fb,
                              const float* __restrict__ ff,
                              float* __restrict__ h0) {
    int p = blockIdx.x * blockDim.x + threadIdx.x;
    if (p >= NB * HW) return;
    int n = p / HW, pix = p % HW;
    int yy = pix / W, xx = pix % W;

    int src_t, cur_t;
    const float* flow;
    if (n < 6) { src_t = n + 1; cur_t = n;     flow = fb + (size_t)n * 2 * HW; }
    else       { int m = n - 6; src_t = m; cur_t = m + 1; flow = ff + (size_t)m * 2 * HW; }

    float fx = flow[pix];
    float fy = flow[HW + pix];
    float px = (float)xx + fx;
    float py = (float)yy + fy;

    float y0f = floorf(py), x0f = floorf(px);
    int iy0 = (int)y0f, ix0 = (int)x0f;
    float wy = py - y0f, wx = px - x0f;
    bool vy0 = (iy0 >= 0) && (iy0 < H);
    bool vy1 = (iy0 + 1 >= 0) && (iy0 + 1 < H);
    bool vx0 = (ix0 >= 0) && (ix0 < W);
    bool vx1 = (ix0 + 1 >= 0) && (ix0 + 1 < W);
    int yc0 = min(max(iy0, 0), H - 1),     yc1 = min(max(iy0 + 1, 0), H - 1);
    int xc0 = min(max(ix0, 0), W - 1),     xc1 = min(max(ix0 + 1, 0), W - 1);
    float w00 = (1.f - wy) * (1.f - wx) * ((vy0 && vx0) ? 1.f : 0.f);
    float w01 = (1.f - wy) * wx          * ((vy0 && vx1) ? 1.f : 0.f);
    float w10 = wy * (1.f - wx)          * ((vy1 && vx0) ? 1.f : 0.f);
    float w11 = wy * wx                  * ((vy1 && vx1) ? 1.f : 0.f);
    int i00 = yc0 * W + xc0, i01 = yc0 * W + xc1;
    int i10 = yc1 * W + xc0, i11 = yc1 * W + xc1;

    const float4* s00 = xt4 + ((size_t)src_t * HW + i00) * (C / 4);
    const float4* s01 = xt4 + ((size_t)src_t * HW + i01) * (C / 4);
    const float4* s10 = xt4 + ((size_t)src_t * HW + i10) * (C / 4);
    const float4* s11 = xt4 + ((size_t)src_t * HW + i11) * (C / 4);
    const float* cur = x + (size_t)cur_t * C * HW;
    float* hn = h0 + (size_t)n * CIN1 * HW;

    #pragma unroll 4
    for (int cb = 0; cb < C / 4; cb++) {
        float4 a = s00[cb], b = s01[cb], c = s10[cb], d = s11[cb];
        float4 v;
        v.x = w00 * a.x + w01 * b.x + w10 * c.x + w11 * d.x;
        v.y = w00 * a.y + w01 * b.y + w10 * c.y + w11 * d.y;
        v.z = w00 * a.z + w01 * b.z + w10 * c.z + w11 * d.z;
        v.w = w00 * a.w + w01 * b.w + w10 * c.w + w11 * d.w;
        hn[(size_t)(4 * cb + 0) * HW + pix] = v.x;
        hn[(size_t)(4 * cb + 1) * HW + pix] = v.y;
        hn[(size_t)(4 * cb + 2) * HW + pix] = v.z;
        hn[(size_t)(4 * cb + 3) * HW + pix] = v.w;
        hn[(size_t)(C + 4 * cb + 0) * HW + pix] = cur[(size_t)(4 * cb + 0) * HW + pix];
        hn[(size_t)(C + 4 * cb + 1) * HW + pix] = cur[(size_t)(4 * cb + 1) * HW + pix];
        hn[(size_t)(C + 4 * cb + 2) * HW + pix] = cur[(size_t)(4 * cb + 2) * HW + pix];
        hn[(size_t)(C + 4 * cb + 3) * HW + pix] = cur[(size_t)(4 * cb + 3) * HW + pix];
    }
    hn[(size_t)128 * HW + pix] = fx;
    hn[(size_t)129 * HW + pix] = fy;
}

// ---------------------------------------------------------------------------
// Direct 3x3 conv, pad 1, NCHW fp32, FFMA2 inner loop (at FFMA2 roofline).
// ---------------------------------------------------------------------------
template<bool RELU>
__global__ __launch_bounds__(128) void conv3x3_k(
    const float* __restrict__ in, const float* __restrict__ wt,
    const float* __restrict__ bias, float* __restrict__ out,
    int Cin, int Cout)
{
    __shared__ float s_in[16][18][34];   // [ci][y][x]   39.2 KB
    __shared__ float s_w[16][9][16];     // [ci][k][co]   9.2 KB

    const int tx = threadIdx.x;
    const int ty = threadIdx.y;
    const int tid = ty * 32 + tx;
    const int x0 = blockIdx.x * 32;
    const int y0 = (blockIdx.y % 6) * 16;
    const int n  = blockIdx.y / 6;
    const int co0 = blockIdx.z * 16;
    const float* inN = in + (size_t)n * Cin * HW;

    unsigned long long acc[4][8];
    #pragma unroll
    for (int r = 0; r < 4; r++)
        #pragma unroll
        for (int o = 0; o < 8; o++) acc[r][o] = 0ull;

    for (int c0 = 0; c0 < Cin; c0 += 16) {
        for (int i = tid; i < 16 * 18 * 34; i += 128) {
            int ci  = i / (18 * 34);
            int rem = i % (18 * 34);
            int iy = rem / 34, ix = rem % 34;
            int gy = y0 + iy - 1, gx = x0 + ix - 1;
            int c = c0 + ci;
            float v = 0.f;
            if (c < Cin && (unsigned)gy < (unsigned)H && (unsigned)gx < (unsigned)W)
                v = inN[(size_t)c * HW + gy * W + gx];
            s_in[ci][iy][ix] = v;
        }
        for (int i = tid; i < 16 * 16 * 9; i += 128) {
            int co = i / 144, rem = i % 144;
            int ci = rem / 9, k = rem % 9;
            int c = c0 + ci;
            s_w[ci][k][co] = (c < Cin) ? wt[((size_t)(co0 + co) * Cin + c) * 9 + k] : 0.f;
        }
        __syncthreads();

        for (int ci = 0; ci < 16; ci++) {
            #pragma unroll
            for (int k = 0; k < 9; k++) {
                const int ky = k / 3, kx = k % 3;
                unsigned long long vv[4];
                #pragma unroll
                for (int r = 0; r < 4; r++) {
                    float v = s_in[ci][ty + 4 * r + ky][tx + kx];
                    vv[r] = pack2(v, v);
                }
                #pragma unroll
                for (int o = 0; o < 8; o++) {
                    unsigned long long wp =
                        *(const unsigned long long*)&s_w[ci][k][2 * o];
                    #pragma unroll
                    for (int r = 0; r < 4; r++)
                        ffma2(acc[r][o], vv[r], wp);
                }
            }
        }
        __syncthreads();
    }

    #pragma unroll
    for (int o = 0; o < 8; o++) {
        float b0 = bias[co0 + 2 * o];
        float b1 = bias[co0 + 2 * o + 1];
        #pragma unroll
        for (int r = 0; r < 4; r++) {
            float2 a = unpack2(acc[r][o]);
            a.x += b0; a.y += b1;
            if (RELU) {
                a.x = (a.x >= 0.f) ? a.x : NEG * a.x;
                a.y = (a.y >= 0.f) ? a.y : NEG * a.y;
            }
            size_t base = (size_t)(y0 + ty + 4 * r) * W + (x0 + tx);
            out[((size_t)n * Cout + co0 + 2 * o)     * HW + base] = a.x;
            out[((size_t)n * Cout + co0 + 2 * o + 1) * HW + base] = a.y;
        }
    }
}

// ---------------------------------------------------------------------------
// Deform stage A: offsets + bilinear sampling -> g_samp[n][576][HW].
// NHWC source: the 4 channels of a deform group are one float4 -> ONE LDG.128
// per bilinear corner (was 4 scalar gathers). 36 gathers/thread instead of 144.
// ---------------------------------------------------------------------------
__global__ __launch_bounds__(128) void sample_k(
    const float4* __restrict__ xt4, const float* __restrict__ fb,
    const float* __restrict__ ff, const float* __restrict__ o4,
    float* __restrict__ samp)
{
    const int pix = blockIdx.x * 128 + threadIdx.x;
    const int dg  = blockIdx.y;
    const int n   = blockIdx.z;
    const int y   = pix / W;
    const int xx  = pix % W;

    int src_t;
    const float* flow;
    if (n < 6) { src_t = n + 1; flow = fb + (size_t)n * 2 * HW; }
    else       { src_t = n - 6; flow = ff + (size_t)(n - 6) * 2 * HW; }
    const float4* srct = xt4 + (size_t)src_t * HW * (C / 4) + dg;  // +pix*16 below
    const float* o4n   = o4 + (size_t)n * COUT4 * HW + pix;
    float*       sampn = samp + (size_t)n * 576 * HW + (size_t)dg * 36 * HW + pix;

    const float fx = flow[pix];
    const float fy = flow[HW + pix];

    #pragma unroll
    for (int kk = 0; kk < 9; kk++) {
        float t0 = o4n[(size_t)(dg * 18 + kk * 2)     * HW];
        float t1 = o4n[(size_t)(dg * 18 + kk * 2 + 1) * HW];
        float tm = o4n[(size_t)(288 + dg * 9 + kk)    * HW];
        float m  = fast_sigmoid(tm);
        float py = 10.f * fast_tanh(t0) + fy + (float)(y  - 1 + kk / 3);
        float px = 10.f * fast_tanh(t1) + fx + (float)(xx - 1 + kk % 3);

        float y0f = floorf(py), x0f = floorf(px);
        int iy0 = (int)y0f, ix0 = (int)x0f;
        float wy = py - y0f, wx = px - x0f;
        bool vy0 = (iy0 >= 0) && (iy0 < H);
        bool vy1 = (iy0 + 1 >= 0) && (iy0 + 1 < H);
        bool vx0 = (ix0 >= 0) && (ix0 < W);
        bool vx1 = (ix0 + 1 >= 0) && (ix0 + 1 < W);
        int yc0 = min(max(iy0, 0), H - 1),     yc1 = min(max(iy0 + 1, 0), H - 1);
        int xc0 = min(max(ix0, 0), W - 1),     xc1 = min(max(ix0 + 1, 0), W - 1);
        float w00 = (1.f - wy) * (1.f - wx) * ((vy0 && vx0) ? m : 0.f);
        float w01 = (1.f - wy) * wx          * ((vy0 && vx1) ? m : 0.f);
        float w10 = wy * (1.f - wx)          * ((vy1 && vx0) ? m : 0.f);
        float w11 = wy * wx                  * ((vy1 && vx1) ? m : 0.f);
        int i00 = yc0 * W + xc0, i01 = yc0 * W + xc1;
        int i10 = yc1 * W + xc0, i11 = yc1 * W + xc1;

        float4 a = srct[(size_t)i00 * (C / 4)];
        float4 b = srct[(size_t)i01 * (C / 4)];
        float4 c = srct[(size_t)i10 * (C / 4)];
        float4 d = srct[(size_t)i11 * (C / 4)];
        float4 v;
        v.x = w00 * a.x + w01 * b.x + w10 * c.x + w11 * d.x;
        v.y = w00 * a.y + w01 * b.y + w10 * c.y + w11 * d.y;
        v.z = w00 * a.z + w01 * b.z + w10 * c.z + w11 * d.z;
        v.w = w00 * a.w + w01 * b.w + w10 * c.w + w11 * d.w;

        sampn[(size_t)(0 * 9 + kk) * HW] = v.x;
        sampn[(size_t)(1 * 9 + kk) * HW] = v.y;
        sampn[(size_t)(2 * 9 + kk) * HW] = v.z;
        sampn[(size_t)(3 * 9 + kk) * HW] = v.w;
    }
}

// ---------------------------------------------------------------------------
// Deform stage B: out[n][64][HW] = W[64][576] @ samp[n][576][HW] + bias.
// Dynamic smem (66.5 KB). Per k step/thread: 6 LDS128 + 32 FFMA2 (=64 MACs).
// ---------------------------------------------------------------------------
#define GEMM_SMEM_FLOATS (64 * 128)
#define GEMM_SMEM_BYTES  (GEMM_SMEM_FLOATS * 4 + 64 * 66 * 8)   // 66,560 B

__global__ __launch_bounds__(128) void gemm_k(
    const float* __restrict__ samp, const float* __restrict__ dw,
    const float* __restrict__ db, float* __restrict__ out)
{
    extern __shared__ float sm[];
    float*  s_s  = sm;                               // [64][128]  32 KB
    float2* s_w2 = (float2*)(sm + GEMM_SMEM_FLOATS); // [64][66]   33.8 KB

    const int tid = threadIdx.x;
    const int pxb = blockIdx.x * 128;
    const int n   = blockIdx.y;
    const float* sampn = samp + (size_t)n * 576 * HW;

    const int pg = tid & 15;    // pixel group: 8 px = 4 f32x2 pairs
    const int og = tid >> 4;    // cout group: 8 couts

    unsigned long long acc[8][4];
    #pragma unroll
    for (int o = 0; o < 8; o++)
        #pragma unroll
        for (int p = 0; p < 4; p++) acc[o][p] = 0ull;

    for (int k0 = 0; k0 < 576; k0 += 64) {
        for (int i = tid; i < 64 * 32; i += 128) {
            int r = i >> 5, c4 = i & 31;
            *(float4*)&s_s[r * 128 + c4 * 4] =
                *(const float4*)&sampn[(size_t)(k0 + r) * HW + pxb + c4 * 4];
        }
        for (int i = tid; i < 64 * 64; i += 128) {
            int co = i >> 6, kk = i & 63;
            float w = dw[(size_t)co * 576 + k0 + kk];
            s_w2[kk * 66 + co] = make_float2(w, w);
        }
        __syncthreads();

        #pragma unroll 2
        for (int kk = 0; kk < 64; kk++) {
            ulonglong2 p0 = *(const ulonglong2*)&s_s[kk * 128 + pg * 8];
            ulonglong2 p1 = *(const ulonglong2*)&s_s[kk * 128 + pg * 8 + 4];
            unsigned long long wq[8];
            #pragma unroll
            for (int j = 0; j < 4; j++) {
                ulonglong2 wv = *(const ulonglong2*)&s_w2[kk * 66 + og * 8 + 2 * j];
                wq[2 * j]     = wv.x;
                wq[2 * j + 1] = wv.y;
            }
            #pragma unroll
            for (int o = 0; o < 8; o++) {
                ffma2(acc[o][0], wq[o], p0.x);
                ffma2(acc[o][1], wq[o], p0.y);
                ffma2(acc[o][2], wq[o], p1.x);
                ffma2(acc[o][3], wq[o], p1.y);
            }
        }
        __syncthreads();
    }

    float* outn = (n < 6) ? out + (size_t)n * C * HW
                          : out + (size_t)(7 + (n - 6) + 1) * C * HW;
    #pragma unroll
    for (int o = 0; o < 8; o++) {
        int co = og * 8 + o;
        float bv = db[co];
        float2 a0 = unpack2(acc[o][0]);
        float2 a1 = unpack2(acc[o][1]);
        float2 a2 = unpack2(acc[o][2]);
        float2 a3 = unpack2(acc[o][3]);
        float4 v0 = make_float4(a0.x + bv, a0.y + bv, a1.x + bv, a1.y + bv);
        float4 v1 = make_float4(a2.x + bv, a2.y + bv, a3.x + bv, a3.y + bv);
        size_t base = (size_t)co * HW + pxb + pg * 8;
        *(float4*)&outn[base]     = v0;
        *(float4*)&outn[base + 4] = v1;
    }
}

// ---------------------------------------------------------------------------
// Launch
// ---------------------------------------------------------------------------
extern "C" void kernel_launch(void* const* d_in, const int* in_sizes, int n_in,
                              void* d_out, int out_size)
{
    const float* x  = (const float*)d_in[0];
    const float* fb = (const float*)d_in[1];
    const float* ff = (const float*)d_in[2];
    const float* w1 = (const float*)d_in[3];  const float* b1 = (const float*)d_in[4];
    const float* w2 = (const float*)d_in[5];  const float* b2 = (const float*)d_in[6];
    const float* w3 = (const float*)d_in[7];  const float* b3 = (const float*)d_in[8];
    const float* w4 = (const float*)d_in[9];  const float* b4 = (const float*)d_in[10];
    const float* dw = (const float*)d_in[11]; const float* db = (const float*)d_in[12];
    float* out = (float*)d_out;

    float *h0, *h1, *h2, *o4, *sp, *xt;
    cudaGetSymbolAddress((void**)&h0, g_h0);
    cudaGetSymbolAddress((void**)&h1, g_h1);
    cudaGetSymbolAddress((void**)&h2, g_h2);
    cudaGetSymbolAddress((void**)&o4, g_o4);
    cudaGetSymbolAddress((void**)&sp, g_samp);
    cudaGetSymbolAddress((void**)&xt, g_xt);

    {   // Zero only frames 6..7 (bwd[6] and fwd[0])
        int n4 = 2 * C * HW / 4;
        zero_k<<<(n4 + 255) / 256, 256>>>((float4*)(out + (size_t)6 * C * HW), n4);
    }
    nhwc_k<<<(T * HW + 127) / 128, 128>>>(x, (float4*)xt);
    warp_concat_k<<<(NB * HW + 255) / 256, 256>>>(x, (const float4*)xt, fb, ff, h0);

    dim3 cb(32, 4);
    conv3x3_k<true ><<<dim3(3, 72, 4),  cb>>>(h0, w1, b1, h1, CIN1, C);
    conv3x3_k<true ><<<dim3(3, 72, 4),  cb>>>(h1, w2, b2, h2, C,    C);
    conv3x3_k<true ><<<dim3(3, 72, 4),  cb>>>(h2, w3, b3, h1, C,    C);
    conv3x3_k<false><<<dim3(3, 72, 27), cb>>>(h1, w4, b4, o4, C, COUT4);

    sample_k<<<dim3(72, 16, NB), 128>>>((const float4*)xt, fb, ff, o4, sp);

    cudaFuncSetAttribute(gemm_k, cudaFuncAttributeMaxDynamicSharedMemorySize,
                         GEMM_SMEM_BYTES);
    gemm_k<<<dim3(72, NB), 128, GEMM_SMEM_BYTES>>>(sp, dw, db, out);
}